// round 8
// baseline (speedup 1.0000x reference)
#include <cuda_runtime.h>
#include <cuda_bf16.h>
#include <math.h>
#include <stdint.h>

#define B_   32
#define L_   256
#define DM_  512
#define FF_  2048
#define E_   8
#define NPAIR 64

// ---------------- device scratch (static = allocation-free) ----------------
__device__ int   g_pair_e[NPAIR];
__device__ float g_pair_g[NPAIR];
// x split:  [B*L][2*DM]   row = [hi(0..511) | lo(0..511)]
__device__ __align__(256) __nv_bfloat16 g_x2[(size_t)B_ * L_ * 2 * DM_];
// W1^T split: [E][FF][2*DM]
__device__ __align__(256) __nv_bfloat16 g_w1t[(size_t)E_ * FF_ * 2 * DM_];
// W2^T split: [E][DM][2*FF]
__device__ __align__(256) __nv_bfloat16 g_w2t[(size_t)E_ * DM_ * 2 * FF_];
// g*gelu(h) split: [pair][L][2*FF]
__device__ __align__(256) __nv_bfloat16 g_gh[(size_t)NPAIR * L_ * 2 * FF_];
// per-pair fp32 partials of GEMM2 (slot-split)
__device__ __align__(256) float g_part[(size_t)NPAIR * L_ * DM_];

// ---------------- helpers ----------------
__device__ __forceinline__ uint32_t smem_u32(const void* p) {
    uint32_t a;
    asm("{ .reg .u64 t; cvta.to.shared.u64 t, %1; cvt.u32.u64 %0, t; }" : "=r"(a) : "l"(p));
    return a;
}
__device__ __forceinline__ void cp16(uint32_t dst, const void* src) {
    asm volatile("cp.async.cg.shared.global [%0], [%1], 16;" :: "r"(dst), "l"(src));
}
#define CP_COMMIT() asm volatile("cp.async.commit_group;" ::: "memory")

__device__ __forceinline__ void ldsm_x4(uint32_t& r0, uint32_t& r1, uint32_t& r2, uint32_t& r3, uint32_t a) {
    asm volatile("ldmatrix.sync.aligned.m8n8.x4.shared.b16 {%0,%1,%2,%3}, [%4];"
                 : "=r"(r0), "=r"(r1), "=r"(r2), "=r"(r3) : "r"(a));
}
__device__ __forceinline__ void mma_bf16(float* c, const uint32_t* a, uint32_t b0, uint32_t b1) {
    asm volatile("mma.sync.aligned.m16n8k16.row.col.f32.bf16.bf16.f32 "
                 "{%0,%1,%2,%3}, {%4,%5,%6,%7}, {%8,%9}, {%0,%1,%2,%3};"
                 : "+f"(c[0]), "+f"(c[1]), "+f"(c[2]), "+f"(c[3])
                 : "r"(a[0]), "r"(a[1]), "r"(a[2]), "r"(a[3]), "r"(b0), "r"(b1));
}
__device__ __forceinline__ float gelu_exact(float x) {
    return 0.5f * x * (1.0f + erff(x * 0.70710678118654752440f));
}

// Load a ROWS x 64 bf16 tile (128B rows, XOR swizzle chunk^=(row&7)) via cp.async.
template<int ROWS, int NT>
__device__ __forceinline__ void load_tile(uint32_t dst, const __nv_bfloat16* src, int ld, int tid) {
    constexpr int ITER = ROWS * 8 / NT;
#pragma unroll
    for (int j = 0; j < ITER; j++) {
        int idx = tid + j * NT;
        int r = idx >> 3, c = idx & 7;
        uint32_t off = (uint32_t)(r * 128 + ((c ^ (r & 7)) * 16));
        cp16(dst + off, (const char*)src + (size_t)r * ld * 2 + c * 16);
    }
}

// Fused 3-term chunk: load Ah/Al/Bh/Bl fragments once, issue AhBh+AlBh+AhBl.
// Warp tile (MF*16) x (NF*8); all four operand tiles are kc=64-wide SMEM tiles.
template<int MF, int NF>
__device__ __forceinline__ void compute_fused(float (&acc)[MF][NF][4],
                                              uint32_t aH, uint32_t aL,
                                              uint32_t bH, uint32_t bL,
                                              int wm, int wn, int lane) {
#pragma unroll
    for (int ks = 0; ks < 4; ks++) {
        uint32_t ah[MF][4], al[MF][4];
#pragma unroll
        for (int mf = 0; mf < MF; mf++) {
            int r = wm + mf * 16 + (lane & 15);
            int c = ks * 2 + (lane >> 4);
            uint32_t off = (uint32_t)(r * 128 + ((c ^ (r & 7)) * 16));
            ldsm_x4(ah[mf][0], ah[mf][1], ah[mf][2], ah[mf][3], aH + off);
            ldsm_x4(al[mf][0], al[mf][1], al[mf][2], al[mf][3], aL + off);
        }
#pragma unroll
        for (int nfp = 0; nfp < NF / 2; nfp++) {
            int q = lane >> 3;
            int r = wn + (nfp * 2 + (q >> 1)) * 8 + (lane & 7);
            int c = ks * 2 + (q & 1);
            uint32_t off = (uint32_t)(r * 128 + ((c ^ (r & 7)) * 16));
            uint32_t bh0, bh1, bh2, bh3, bl0, bl1, bl2, bl3;
            ldsm_x4(bh0, bh1, bh2, bh3, bH + off);
            ldsm_x4(bl0, bl1, bl2, bl3, bL + off);
#pragma unroll
            for (int mf = 0; mf < MF; mf++) {
                mma_bf16(acc[mf][2 * nfp],     ah[mf], bh0, bh1);
                mma_bf16(acc[mf][2 * nfp + 1], ah[mf], bh2, bh3);
                mma_bf16(acc[mf][2 * nfp],     al[mf], bh0, bh1);
                mma_bf16(acc[mf][2 * nfp + 1], al[mf], bh2, bh3);
                mma_bf16(acc[mf][2 * nfp],     ah[mf], bl0, bl1);
                mma_bf16(acc[mf][2 * nfp + 1], ah[mf], bl2, bl3);
            }
        }
    }
}

// ---------------------------------------------------------------------------
// gates
// ---------------------------------------------------------------------------
__global__ void gates_kernel(const float* __restrict__ logits, const int* __restrict__ masks) {
    int b = threadIdx.x;
    if (b >= B_) return;
    float p[E_];
    float mx = -1e30f;
#pragma unroll
    for (int i = 0; i < E_; i++) { p[i] = logits[b * E_ + i]; mx = fmaxf(mx, p[i]); }
    float s = 0.0f;
#pragma unroll
    for (int i = 0; i < E_; i++) { p[i] = expf(p[i] - mx); s += p[i]; }
    float inv = 1.0f / s;
#pragma unroll
    for (int i = 0; i < E_; i++) p[i] = (masks[b * E_ + i] == 1) ? p[i] * inv : 0.0f;
    int i1 = 0;
#pragma unroll
    for (int i = 1; i < E_; i++) if (p[i] > p[i1]) i1 = i;
    int i2 = -1;
#pragma unroll
    for (int i = 0; i < E_; i++) {
        if (i == i1) continue;
        if (i2 < 0 || p[i] > p[i2]) i2 = i;
    }
    float denom = p[i1] + p[i2] + 1e-9f;
    g_pair_e[2 * b + 0] = i1;  g_pair_g[2 * b + 0] = p[i1] / denom;
    g_pair_e[2 * b + 1] = i2;  g_pair_g[2 * b + 1] = p[i2] / denom;
}

// ---------------------------------------------------------------------------
// prep kernels (device-symbol writes from device code only)
// ---------------------------------------------------------------------------
__global__ void cvt_split_kernel(const float* __restrict__ X) {
    size_t i = (size_t)blockIdx.x * blockDim.x + threadIdx.x;
    if (i >= (size_t)B_ * L_ * DM_) return;
    size_t row = i / DM_;
    int k = (int)(i % DM_);
    float v = X[i];
    __nv_bfloat16 h = __float2bfloat16(v);
    g_x2[row * (2 * DM_) + k] = h;
    g_x2[row * (2 * DM_) + DM_ + k] = __float2bfloat16(v - __bfloat162float(h));
}

template<int K, int N>
__device__ __forceinline__ void transpose_cvt_body(const float* __restrict__ W,
                                                   __nv_bfloat16* __restrict__ T) {
    __shared__ float s[32][33];
    int e = blockIdx.z;
    int n0 = blockIdx.x * 32, k0 = blockIdx.y * 32;
    const float* Wp = W + (size_t)e * K * N;
#pragma unroll
    for (int i = 0; i < 32; i += 8)
        s[threadIdx.y + i][threadIdx.x] = Wp[(size_t)(k0 + threadIdx.y + i) * N + n0 + threadIdx.x];
    __syncthreads();
#pragma unroll
    for (int i = 0; i < 32; i += 8) {
        int n = n0 + threadIdx.y + i;
        int k = k0 + threadIdx.x;
        float v = s[threadIdx.x][threadIdx.y + i];
        __nv_bfloat16 h = __float2bfloat16(v);
        __nv_bfloat16* rowp = T + ((size_t)e * N + n) * (2 * (size_t)K);
        rowp[k]     = h;
        rowp[K + k] = __float2bfloat16(v - __bfloat162float(h));
    }
}
__global__ void transpose_cvt_w1(const float* __restrict__ W) {
    transpose_cvt_body<DM_, FF_>(W, g_w1t);
}
__global__ void transpose_cvt_w2(const float* __restrict__ W) {
    transpose_cvt_body<FF_, DM_>(W, g_w2t);
}

// ---------------------------------------------------------------------------
// GEMM1: gh[pair] = g * gelu(x[b] @ W1[e] + b1[e]) -> bf16 hi/lo rows of 4096
// BM=128, BN=128, kc=64; stage = 64KB; 3 stages (192KB), 1 sync/iter.
// 512 threads, 16 warps 4x4, warp tile 32x32. Grid (16,2,64) = 2048 CTAs.
// ---------------------------------------------------------------------------
#define GS_STAGE  65536u
#define GS_A_L    16384u
#define GS_B_H    32768u
#define GS_B_L    49152u
#define GS_SMEM   (3 * 65536)

__global__ void __launch_bounds__(512, 1)
gemm1_mma(const float* __restrict__ b1p) {
    extern __shared__ __align__(128) char smem[];
    const int tid = threadIdx.x, lane = tid & 31, wid = tid >> 5;
    const int pair = blockIdx.z;
    const int e = g_pair_e[pair];
    const float g = g_pair_g[pair];
    const int m0 = blockIdx.y * 128, n0 = blockIdx.x * 128;

    const __nv_bfloat16* Abase = g_x2  + ((size_t)(pair >> 1) * L_ + m0) * (2 * DM_);
    const __nv_bfloat16* Bbase = g_w1t + ((size_t)e * FF_ + n0) * (2 * DM_);

    uint32_t s0 = smem_u32(smem);
    const int wm = (wid >> 2) * 32, wn = (wid & 3) * 32;   // warp tile 32x32

    float acc[2][4][4] = {};
    const int NC = 8;   // 512 / 64

#define G1_LOAD(c, buf) do { int _k = (c) * 64; uint32_t _d = s0 + (buf) * GS_STAGE; \
        load_tile<128, 512>(_d,          Abase + _k,       2 * DM_, tid); \
        load_tile<128, 512>(_d + GS_A_L, Abase + DM_ + _k, 2 * DM_, tid); \
        load_tile<128, 512>(_d + GS_B_H, Bbase + _k,       2 * DM_, tid); \
        load_tile<128, 512>(_d + GS_B_L, Bbase + DM_ + _k, 2 * DM_, tid); \
        CP_COMMIT(); } while (0)

    G1_LOAD(0, 0);
    G1_LOAD(1, 1);
    for (int c = 0; c < NC; c++) {
        if (c == NC - 1) asm volatile("cp.async.wait_group 0;" ::: "memory");
        else             asm volatile("cp.async.wait_group 1;" ::: "memory");
        __syncthreads();   // tile c visible; all warps done with buf (c+2)%3 (last read at c-1)
        if (c + 2 < NC) G1_LOAD(c + 2, (uint32_t)((c + 2) % 3));
        uint32_t sb = s0 + (uint32_t)(c % 3) * GS_STAGE;
        compute_fused<2, 4>(acc, sb, sb + GS_A_L, sb + GS_B_H, sb + GS_B_L, wm, wn, lane);
    }
#undef G1_LOAD

    // epilogue: +bias, gelu, *gate, split hi/lo, store
    const float* b1e = b1p + (size_t)e * FF_;
#pragma unroll
    for (int mf = 0; mf < 2; mf++) {
#pragma unroll
        for (int h = 0; h < 2; h++) {
            int r = m0 + wm + mf * 16 + (lane >> 2) + 8 * h;
            __nv_bfloat16* rowp = g_gh + ((size_t)pair * L_ + r) * (2 * FF_);
#pragma unroll
            for (int nf = 0; nf < 4; nf++) {
                int n = n0 + wn + nf * 8 + (lane & 3) * 2;
                float v0 = acc[mf][nf][2 * h + 0] + __ldg(b1e + n);
                float v1 = acc[mf][nf][2 * h + 1] + __ldg(b1e + n + 1);
                v0 = gelu_exact(v0) * g;
                v1 = gelu_exact(v1) * g;
                __nv_bfloat16 h0 = __float2bfloat16(v0), h1 = __float2bfloat16(v1);
                __nv_bfloat162 hv; hv.x = h0; hv.y = h1;
                __nv_bfloat162 lv;
                lv.x = __float2bfloat16(v0 - __bfloat162float(h0));
                lv.y = __float2bfloat16(v1 - __bfloat162float(h1));
                *(__nv_bfloat162*)(rowp + n)       = hv;
                *(__nv_bfloat162*)(rowp + FF_ + n) = lv;
            }
        }
    }
}

// ---------------------------------------------------------------------------
// GEMM2 (slot-split): part[pair] = (g*h)[pair] @ W2[e_pair]   (fp32 partials)
// BM=128, BN=128, kc=64; 3 stages, 1 sync/iter; K = 2048 (32 chunks).
// 512 threads, warp tile 32x32. Grid (4,2,64) = 512 CTAs.
// ---------------------------------------------------------------------------
__global__ void __launch_bounds__(512, 1)
gemm2_mma() {
    extern __shared__ __align__(128) char smem[];
    const int tid = threadIdx.x, lane = tid & 31, wid = tid >> 5;
    const int pair = blockIdx.z;
    const int e = g_pair_e[pair];
    const int m0 = blockIdx.y * 128, n0 = blockIdx.x * 128;

    const __nv_bfloat16* Abase = g_gh  + ((size_t)pair * L_ + m0) * (2 * FF_);
    const __nv_bfloat16* Bbase = g_w2t + ((size_t)e * DM_ + n0) * (2 * FF_);

    uint32_t s0 = smem_u32(smem);
    const int wm = (wid >> 2) * 32, wn = (wid & 3) * 32;   // warp tile 32x32

    float acc[2][4][4] = {};
    const int NC = 32;   // 2048 / 64

#define G2_LOAD(c, buf) do { int _k = (c) * 64; uint32_t _d = s0 + (buf) * GS_STAGE; \
        load_tile<128, 512>(_d,          Abase + _k,       2 * FF_, tid); \
        load_tile<128, 512>(_d + GS_A_L, Abase + FF_ + _k, 2 * FF_, tid); \
        load_tile<128, 512>(_d + GS_B_H, Bbase + _k,       2 * FF_, tid); \
        load_tile<128, 512>(_d + GS_B_L, Bbase + FF_ + _k, 2 * FF_, tid); \
        CP_COMMIT(); } while (0)

    G2_LOAD(0, 0);
    G2_LOAD(1, 1);
    for (int c = 0; c < NC; c++) {
        if (c == NC - 1) asm volatile("cp.async.wait_group 0;" ::: "memory");
        else             asm volatile("cp.async.wait_group 1;" ::: "memory");
        __syncthreads();
        if (c + 2 < NC) G2_LOAD(c + 2, (uint32_t)((c + 2) % 3));
        uint32_t sb = s0 + (uint32_t)(c % 3) * GS_STAGE;
        compute_fused<2, 4>(acc, sb, sb + GS_A_L, sb + GS_B_H, sb + GS_B_L, wm, wn, lane);
    }
#undef G2_LOAD

    // store fp32 partials (no bias here; combine kernel adds it)
#pragma unroll
    for (int mf = 0; mf < 2; mf++) {
#pragma unroll
        for (int h = 0; h < 2; h++) {
            int r = wm + mf * 16 + (lane >> 2) + 8 * h;
            float* op = g_part + ((size_t)pair * L_ + m0 + r) * DM_;
#pragma unroll
            for (int nf = 0; nf < 4; nf++) {
                int n = n0 + wn + nf * 8 + (lane & 3) * 2;
                float2 v;
                v.x = acc[mf][nf][2 * h + 0];
                v.y = acc[mf][nf][2 * h + 1];
                *(float2*)(op + n) = v;
            }
        }
    }
}

// ---------------------------------------------------------------------------
// combine: out[b,l,:] = part[2b] + part[2b+1] + g0*b2[e0] + g1*b2[e1]
// ---------------------------------------------------------------------------
__global__ void combine_kernel(const float* __restrict__ b2p, float* __restrict__ out) {
    // one float4 per thread; total B*L*DM/4 = 1,048,576
    size_t i = (size_t)blockIdx.x * blockDim.x + threadIdx.x;
    size_t row = i / (DM_ / 4);        // b * L + l
    int n4 = (int)(i % (DM_ / 4));
    int b = (int)(row / L_);
    int e0 = g_pair_e[2 * b + 0], e1 = g_pair_e[2 * b + 1];
    float g0 = g_pair_g[2 * b + 0], g1 = g_pair_g[2 * b + 1];

    const float4* p0 = (const float4*)(g_part + ((size_t)(2 * b + 0) * L_ + (row % L_)) * DM_);
    const float4* p1 = (const float4*)(g_part + ((size_t)(2 * b + 1) * L_ + (row % L_)) * DM_);
    const float4* bb0 = (const float4*)(b2p + (size_t)e0 * DM_);
    const float4* bb1 = (const float4*)(b2p + (size_t)e1 * DM_);

    float4 a = p0[n4], c = p1[n4], d0 = __ldg(bb0 + n4), d1 = __ldg(bb1 + n4);
    float4 r;
    r.x = a.x + c.x + g0 * d0.x + g1 * d1.x;
    r.y = a.y + c.y + g0 * d0.y + g1 * d1.y;
    r.z = a.z + c.z + g0 * d0.z + g1 * d1.z;
    r.w = a.w + c.w + g0 * d0.w + g1 * d1.w;
    ((float4*)out)[i] = r;
}

// ---------------------------------------------------------------------------
// launch — kernel launches + idempotent attribute opt-ins (no statics)
// ---------------------------------------------------------------------------
extern "C" void kernel_launch(void* const* d_in, const int* in_sizes, int n_in,
                              void* d_out, int out_size) {
    const float* x      = (const float*)d_in[0];
    const float* logits = (const float*)d_in[1];
    const int*   masks  = (const int*)  d_in[2];
    const float* W1     = (const float*)d_in[3];
    const float* b1     = (const float*)d_in[4];
    const float* W2     = (const float*)d_in[5];
    const float* b2     = (const float*)d_in[6];
    float* out = (float*)d_out;

    cudaFuncSetAttribute(gemm1_mma, cudaFuncAttributeMaxDynamicSharedMemorySize, GS_SMEM);
    cudaFuncSetAttribute(gemm2_mma, cudaFuncAttributeMaxDynamicSharedMemorySize, GS_SMEM);

    gates_kernel<<<1, 32>>>(logits, masks);

    size_t nx = (size_t)B_ * L_ * DM_;
    cvt_split_kernel<<<(unsigned)((nx + 255) / 256), 256>>>(x);

    dim3 tb(32, 8);
    transpose_cvt_w1<<<dim3(FF_ / 32, DM_ / 32, E_), tb>>>(W1);
    transpose_cvt_w2<<<dim3(DM_ / 32, FF_ / 32, E_), tb>>>(W2);

    gemm1_mma<<<dim3(FF_ / 128, L_ / 128, NPAIR), 512, GS_SMEM>>>(b1);
    gemm2_mma<<<dim3(DM_ / 128, L_ / 128, NPAIR), 512, GS_SMEM>>>();

    size_t nq = (size_t)B_ * L_ * DM_ / 4;
    combine_kernel<<<(unsigned)((nq + 255) / 256), 256>>>(b2, out);
}

// round 9
// speedup vs baseline: 1.1285x; 1.1285x over previous
#include <cuda_runtime.h>
#include <cuda_bf16.h>
#include <math.h>
#include <stdint.h>

#define B_   32
#define L_   256
#define DM_  512
#define FF_  2048
#define E_   8
#define NPAIR 64

// ---------------- device scratch (static = allocation-free) ----------------
__device__ int   g_pair_e[NPAIR];
__device__ float g_pair_g[NPAIR];
// x split:  [B*L][2*DM]   row = [hi(0..511) | lo(0..511)]
__device__ __align__(256) __nv_bfloat16 g_x2[(size_t)B_ * L_ * 2 * DM_];
// W1^T split: [E][FF][2*DM]
__device__ __align__(256) __nv_bfloat16 g_w1t[(size_t)E_ * FF_ * 2 * DM_];
// W2^T split: [E][DM][2*FF]
__device__ __align__(256) __nv_bfloat16 g_w2t[(size_t)E_ * DM_ * 2 * FF_];
// g*gelu(h) split: [pair][L][2*FF]
__device__ __align__(256) __nv_bfloat16 g_gh[(size_t)NPAIR * L_ * 2 * FF_];

// ---------------- helpers ----------------
__device__ __forceinline__ uint32_t smem_u32(const void* p) {
    uint32_t a;
    asm("{ .reg .u64 t; cvta.to.shared.u64 t, %1; cvt.u32.u64 %0, t; }" : "=r"(a) : "l"(p));
    return a;
}
__device__ __forceinline__ void cp16(uint32_t dst, const void* src) {
    asm volatile("cp.async.cg.shared.global [%0], [%1], 16;" :: "r"(dst), "l"(src));
}
#define CP_COMMIT() asm volatile("cp.async.commit_group;" ::: "memory")

__device__ __forceinline__ void ldsm_x4(uint32_t& r0, uint32_t& r1, uint32_t& r2, uint32_t& r3, uint32_t a) {
    asm volatile("ldmatrix.sync.aligned.m8n8.x4.shared.b16 {%0,%1,%2,%3}, [%4];"
                 : "=r"(r0), "=r"(r1), "=r"(r2), "=r"(r3) : "r"(a));
}
__device__ __forceinline__ void mma_bf16(float* c, const uint32_t* a, uint32_t b0, uint32_t b1) {
    asm volatile("mma.sync.aligned.m16n8k16.row.col.f32.bf16.bf16.f32 "
                 "{%0,%1,%2,%3}, {%4,%5,%6,%7}, {%8,%9}, {%0,%1,%2,%3};"
                 : "+f"(c[0]), "+f"(c[1]), "+f"(c[2]), "+f"(c[3])
                 : "r"(a[0]), "r"(a[1]), "r"(a[2]), "r"(a[3]), "r"(b0), "r"(b1));
}
__device__ __forceinline__ float gelu_exact(float x) {
    return 0.5f * x * (1.0f + erff(x * 0.70710678118654752440f));
}

// Load a ROWS x 64 bf16 tile (128B rows, XOR swizzle chunk^=(row&7)) via cp.async.
template<int ROWS, int NT>
__device__ __forceinline__ void load_tile(uint32_t dst, const __nv_bfloat16* src, int ld, int tid) {
    constexpr int ITER = ROWS * 8 / NT;
#pragma unroll
    for (int j = 0; j < ITER; j++) {
        int idx = tid + j * NT;
        int r = idx >> 3, c = idx & 7;
        uint32_t off = (uint32_t)(r * 128 + ((c ^ (r & 7)) * 16));
        cp16(dst + off, (const char*)src + (size_t)r * ld * 2 + c * 16);
    }
}

// Fused 3-term chunk: load Ah/Al/Bh/Bl fragments once, issue AhBh+AlBh+AhBl.
template<int MF, int NF>
__device__ __forceinline__ void compute_fused(float (&acc)[MF][NF][4],
                                              uint32_t aH, uint32_t aL,
                                              uint32_t bH, uint32_t bL,
                                              int wm, int wn, int lane) {
#pragma unroll
    for (int ks = 0; ks < 4; ks++) {
        uint32_t ah[MF][4], al[MF][4];
#pragma unroll
        for (int mf = 0; mf < MF; mf++) {
            int r = wm + mf * 16 + (lane & 15);
            int c = ks * 2 + (lane >> 4);
            uint32_t off = (uint32_t)(r * 128 + ((c ^ (r & 7)) * 16));
            ldsm_x4(ah[mf][0], ah[mf][1], ah[mf][2], ah[mf][3], aH + off);
            ldsm_x4(al[mf][0], al[mf][1], al[mf][2], al[mf][3], aL + off);
        }
#pragma unroll
        for (int nfp = 0; nfp < NF / 2; nfp++) {
            int q = lane >> 3;
            int r = wn + (nfp * 2 + (q >> 1)) * 8 + (lane & 7);
            int c = ks * 2 + (q & 1);
            uint32_t off = (uint32_t)(r * 128 + ((c ^ (r & 7)) * 16));
            uint32_t bh0, bh1, bh2, bh3, bl0, bl1, bl2, bl3;
            ldsm_x4(bh0, bh1, bh2, bh3, bH + off);
            ldsm_x4(bl0, bl1, bl2, bl3, bL + off);
#pragma unroll
            for (int mf = 0; mf < MF; mf++) {
                mma_bf16(acc[mf][2 * nfp],     ah[mf], bh0, bh1);
                mma_bf16(acc[mf][2 * nfp + 1], ah[mf], bh2, bh3);
                mma_bf16(acc[mf][2 * nfp],     al[mf], bh0, bh1);
                mma_bf16(acc[mf][2 * nfp + 1], al[mf], bh2, bh3);
                mma_bf16(acc[mf][2 * nfp],     ah[mf], bl0, bl1);
                mma_bf16(acc[mf][2 * nfp + 1], ah[mf], bl2, bl3);
            }
        }
    }
}

// ---------------------------------------------------------------------------
// Fused prep: gates + x hi/lo split + W1^T split + W2^T split in ONE launch.
// All four sections are mutually independent; partitioned by blockIdx.x.
//   [0, 16384)        : x split (256 elems per block)
//   [16384, 24576)    : W1 transpose tiles (64 x 16 x 8)
//   [24576, 32768)    : W2 transpose tiles (16 x 64 x 8)
//   [32768]           : gates (first 32 threads)
// ---------------------------------------------------------------------------
__device__ __forceinline__ void transpose_sec(const float* __restrict__ W,
                                              __nv_bfloat16* __restrict__ T,
                                              int K, int N, int bx, int by, int bz,
                                              int tx, int ty, float (*s)[33]) {
    int n0 = bx * 32, k0 = by * 32;
    const float* Wp = W + (size_t)bz * K * N;
#pragma unroll
    for (int i = 0; i < 32; i += 8)
        s[ty + i][tx] = Wp[(size_t)(k0 + ty + i) * N + n0 + tx];
    __syncthreads();
#pragma unroll
    for (int i = 0; i < 32; i += 8) {
        int n = n0 + ty + i;
        int k = k0 + tx;
        float v = s[tx][ty + i];
        __nv_bfloat16 h = __float2bfloat16(v);
        __nv_bfloat16* rowp = T + ((size_t)bz * N + n) * (2 * (size_t)K);
        rowp[k]     = h;
        rowp[K + k] = __float2bfloat16(v - __bfloat162float(h));
    }
}

__global__ void prep_kernel(const float* __restrict__ X,
                            const float* __restrict__ logits,
                            const int*   __restrict__ masks,
                            const float* __restrict__ W1,
                            const float* __restrict__ W2) {
    __shared__ float s[32][33];
    const int blk = blockIdx.x;
    const int tid = threadIdx.x;
    const int tx = tid & 31, ty = tid >> 5;

    if (blk < 16384) {
        // x split
        size_t i = (size_t)blk * 256 + tid;
        size_t row = i / DM_;
        int k = (int)(i % DM_);
        float v = X[i];
        __nv_bfloat16 h = __float2bfloat16(v);
        g_x2[row * (2 * DM_) + k] = h;
        g_x2[row * (2 * DM_) + DM_ + k] = __float2bfloat16(v - __bfloat162float(h));
    } else if (blk < 24576) {
        int i = blk - 16384;                       // W1: bx<64, by<16, bz<8
        transpose_sec(W1, g_w1t, DM_, FF_, i & 63, (i >> 6) & 15, i >> 10, tx, ty, s);
    } else if (blk < 32768) {
        int i = blk - 24576;                       // W2: bx<16, by<64, bz<8
        transpose_sec(W2, g_w2t, FF_, DM_, i & 15, (i >> 4) & 63, i >> 10, tx, ty, s);
    } else {
        // gates
        int b = tid;
        if (b >= B_) return;
        float p[E_];
        float mx = -1e30f;
#pragma unroll
        for (int i = 0; i < E_; i++) { p[i] = logits[b * E_ + i]; mx = fmaxf(mx, p[i]); }
        float sum = 0.0f;
#pragma unroll
        for (int i = 0; i < E_; i++) { p[i] = expf(p[i] - mx); sum += p[i]; }
        float inv = 1.0f / sum;
#pragma unroll
        for (int i = 0; i < E_; i++) p[i] = (masks[b * E_ + i] == 1) ? p[i] * inv : 0.0f;
        int i1 = 0;
#pragma unroll
        for (int i = 1; i < E_; i++) if (p[i] > p[i1]) i1 = i;
        int i2 = -1;
#pragma unroll
        for (int i = 0; i < E_; i++) {
            if (i == i1) continue;
            if (i2 < 0 || p[i] > p[i2]) i2 = i;
        }
        float denom = p[i1] + p[i2] + 1e-9f;
        g_pair_e[2 * b + 0] = i1;  g_pair_g[2 * b + 0] = p[i1] / denom;
        g_pair_e[2 * b + 1] = i2;  g_pair_g[2 * b + 1] = p[i2] / denom;
    }
}

// ---------------------------------------------------------------------------
// GEMM1 (R7 config): gh[pair] = g * gelu(x[b] @ W1[e] + b1[e])
// BM=128, BN=256, kc=64; stage = Ah16+Al16+Bh32+Bl32 = 96KB; 2 stages (192KB)
// 512 threads, 16 warps 4x4, warp tile 32x64 (MF=2, NF=8). Grid (8,2,64).
// ---------------------------------------------------------------------------
#define G1_STAGE  98304u
#define G1_A_L    16384u
#define G1_B_H    32768u
#define G1_B_L    65536u
#define G1_SMEM   (2 * 98304)

__global__ void __launch_bounds__(512, 1)
gemm1_mma(const float* __restrict__ b1p) {
    extern __shared__ __align__(128) char smem[];
    const int tid = threadIdx.x, lane = tid & 31, wid = tid >> 5;
    const int pair = blockIdx.z;
    const int e = g_pair_e[pair];
    const float g = g_pair_g[pair];
    const int m0 = blockIdx.y * 128, n0 = blockIdx.x * 256;

    const __nv_bfloat16* Abase = g_x2  + ((size_t)(pair >> 1) * L_ + m0) * (2 * DM_);
    const __nv_bfloat16* Bbase = g_w1t + ((size_t)e * FF_ + n0) * (2 * DM_);

    uint32_t s0 = smem_u32(smem);
    const int wm = (wid >> 2) * 32, wn = (wid & 3) * 64;   // warp tile 32x64

    float acc[2][8][4] = {};
    const int NC = 8;   // 512 / 64

#define G1_LOAD(c, buf) do { int _k = (c) * 64; uint32_t _d = s0 + (buf) * G1_STAGE; \
        load_tile<128, 512>(_d,          Abase + _k,       2 * DM_, tid); \
        load_tile<128, 512>(_d + G1_A_L, Abase + DM_ + _k, 2 * DM_, tid); \
        load_tile<256, 512>(_d + G1_B_H, Bbase + _k,       2 * DM_, tid); \
        load_tile<256, 512>(_d + G1_B_L, Bbase + DM_ + _k, 2 * DM_, tid); \
        CP_COMMIT(); } while (0)

    G1_LOAD(0, 0);
    G1_LOAD(1, 1);
    for (int c = 0; c < NC; c++) {
        if (c == NC - 1) asm volatile("cp.async.wait_group 0;" ::: "memory");
        else             asm volatile("cp.async.wait_group 1;" ::: "memory");
        __syncthreads();
        uint32_t sb = s0 + (uint32_t)(c & 1) * G1_STAGE;
        compute_fused<2, 8>(acc, sb, sb + G1_A_L, sb + G1_B_H, sb + G1_B_L, wm, wn, lane);
        __syncthreads();
        if (c + 2 < NC) G1_LOAD(c + 2, (c + 2) & 1);
    }
#undef G1_LOAD

    // epilogue: +bias, gelu, *gate, split hi/lo, store
    const float* b1e = b1p + (size_t)e * FF_;
#pragma unroll
    for (int mf = 0; mf < 2; mf++) {
#pragma unroll
        for (int h = 0; h < 2; h++) {
            int r = m0 + wm + mf * 16 + (lane >> 2) + 8 * h;
            __nv_bfloat16* rowp = g_gh + ((size_t)pair * L_ + r) * (2 * FF_);
#pragma unroll
            for (int nf = 0; nf < 8; nf++) {
                int n = n0 + wn + nf * 8 + (lane & 3) * 2;
                float v0 = acc[mf][nf][2 * h + 0] + __ldg(b1e + n);
                float v1 = acc[mf][nf][2 * h + 1] + __ldg(b1e + n + 1);
                v0 = gelu_exact(v0) * g;
                v1 = gelu_exact(v1) * g;
                __nv_bfloat16 h0 = __float2bfloat16(v0), h1 = __float2bfloat16(v1);
                __nv_bfloat162 hv; hv.x = h0; hv.y = h1;
                __nv_bfloat162 lv;
                lv.x = __float2bfloat16(v0 - __bfloat162float(h0));
                lv.y = __float2bfloat16(v1 - __bfloat162float(h1));
                *(__nv_bfloat162*)(rowp + n)       = hv;
                *(__nv_bfloat162*)(rowp + FF_ + n) = lv;
            }
        }
    }
}

// ---------------------------------------------------------------------------
// GEMM2: out[b] = sum_slot (g*h)[b,slot] @ W2[e_slot] + gated bias
// BM=128, BN=64, kc=64; stage = Ah16+Al16+Bh8+Bl8 = 48KB; 2 stages (96KB)
// 256 threads, 8 warps 4x2, warp tile 32x32 -> 2 CTAs/SM co-resident.
// virtual K = 2 slots * 2048 (64 chunks); grid (8,2,32) = 512 CTAs.
// ---------------------------------------------------------------------------
#define H2_STAGE  49152u
#define H2_A_L    16384u
#define H2_B_H    32768u
#define H2_B_L    40960u
#define H2_SMEM   (2 * 49152)

__global__ void __launch_bounds__(256, 2)
gemm2_mma(const float* __restrict__ b2p, float* __restrict__ out) {
    extern __shared__ __align__(128) char smem[];
    const int tid = threadIdx.x, lane = tid & 31, wid = tid >> 5;
    const int bb = blockIdx.z;
    const int m0 = blockIdx.y * 128, n0 = blockIdx.x * 64;
    const int e0 = g_pair_e[2 * bb + 0], e1 = g_pair_e[2 * bb + 1];
    const float g0 = g_pair_g[2 * bb + 0], g1 = g_pair_g[2 * bb + 1];

    const __nv_bfloat16* Ab[2] = {
        g_gh + ((size_t)(2 * bb + 0) * L_ + m0) * (2 * FF_),
        g_gh + ((size_t)(2 * bb + 1) * L_ + m0) * (2 * FF_)
    };
    const __nv_bfloat16* Bb[2] = {
        g_w2t + ((size_t)e0 * DM_ + n0) * (2 * FF_),
        g_w2t + ((size_t)e1 * DM_ + n0) * (2 * FF_)
    };

    uint32_t s0 = smem_u32(smem);
    const int wm = (wid >> 1) * 32, wn = (wid & 1) * 32;   // warp tile 32x32

    float acc[2][4][4] = {};
    const int NC = 64;   // 2 slots * (2048/64)

#define G2_LOAD(c, buf) do { \
        int _sl = (c) >> 5; int _k = ((c) & 31) * 64; uint32_t _d = s0 + (buf) * H2_STAGE; \
        load_tile<128, 256>(_d,          Ab[_sl] + _k,       2 * FF_, tid); \
        load_tile<128, 256>(_d + H2_A_L, Ab[_sl] + FF_ + _k, 2 * FF_, tid); \
        load_tile<64, 256> (_d + H2_B_H, Bb[_sl] + _k,       2 * FF_, tid); \
        load_tile<64, 256> (_d + H2_B_L, Bb[_sl] + FF_ + _k, 2 * FF_, tid); \
        CP_COMMIT(); } while (0)

    G2_LOAD(0, 0);
    G2_LOAD(1, 1);
    for (int c = 0; c < NC; c++) {
        if (c == NC - 1) asm volatile("cp.async.wait_group 0;" ::: "memory");
        else             asm volatile("cp.async.wait_group 1;" ::: "memory");
        __syncthreads();
        uint32_t sb = s0 + (uint32_t)(c & 1) * H2_STAGE;
        compute_fused<2, 4>(acc, sb, sb + H2_A_L, sb + H2_B_H, sb + H2_B_L, wm, wn, lane);
        __syncthreads();
        if (c + 2 < NC) G2_LOAD(c + 2, (c + 2) & 1);
    }
#undef G2_LOAD

    const float* b2e0 = b2p + (size_t)e0 * DM_;
    const float* b2e1 = b2p + (size_t)e1 * DM_;
#pragma unroll
    for (int mf = 0; mf < 2; mf++) {
#pragma unroll
        for (int h = 0; h < 2; h++) {
            int r = m0 + wm + mf * 16 + (lane >> 2) + 8 * h;
            float* op = out + ((size_t)bb * L_ + r) * DM_;
#pragma unroll
            for (int nf = 0; nf < 4; nf++) {
                int n = n0 + wn + nf * 8 + (lane & 3) * 2;
                float2 v;
                v.x = acc[mf][nf][2 * h + 0] + g0 * __ldg(b2e0 + n)     + g1 * __ldg(b2e1 + n);
                v.y = acc[mf][nf][2 * h + 1] + g0 * __ldg(b2e0 + n + 1) + g1 * __ldg(b2e1 + n + 1);
                *(float2*)(op + n) = v;
            }
        }
    }
}

// ---------------------------------------------------------------------------
// launch — kernel launches + idempotent attribute opt-ins (no statics)
// ---------------------------------------------------------------------------
extern "C" void kernel_launch(void* const* d_in, const int* in_sizes, int n_in,
                              void* d_out, int out_size) {
    const float* x      = (const float*)d_in[0];
    const float* logits = (const float*)d_in[1];
    const int*   masks  = (const int*)  d_in[2];
    const float* W1     = (const float*)d_in[3];
    const float* b1     = (const float*)d_in[4];
    const float* W2     = (const float*)d_in[5];
    const float* b2     = (const float*)d_in[6];
    float* out = (float*)d_out;

    cudaFuncSetAttribute(gemm1_mma, cudaFuncAttributeMaxDynamicSharedMemorySize, G1_SMEM);
    cudaFuncSetAttribute(gemm2_mma, cudaFuncAttributeMaxDynamicSharedMemorySize, H2_SMEM);

    prep_kernel<<<32769, 256>>>(x, logits, masks, W1, W2);

    gemm1_mma<<<dim3(FF_ / 256, L_ / 128, NPAIR), 512, G1_SMEM>>>(b1);
    gemm2_mma<<<dim3(DM_ / 64, L_ / 128, B_), 256, H2_SMEM>>>(b2, out);
}